// round 1
// baseline (speedup 1.0000x reference)
#include <cuda_runtime.h>
#include <math.h>
#include <stdint.h>

// ---------------- problem constants ----------------
constexpr int Bb   = 32;
constexpr int Nn   = 196;
constexpr int Cc   = 768;
constexpr int Hh   = 12;
constexpr int Ll   = 4;
constexpr int DFF  = 3072;
constexpr int HD   = Cc / Hh;          // 64
constexpr int ROWS = Bb * Nn;          // 6272
constexpr int NCAT = 2 * Nn;           // 392

// ---------------- scratch (static device memory; no allocation) ----------------
__device__ float g_fused[Bb * Ll * Cc];          // [B,L,C]
__device__ float g_h   [ROWS * Cc];              // LN output
__device__ float g_qkv [ROWS * 3 * Cc];          // qkv projection
__device__ float g_o   [ROWS * Cc];              // attention output (B,N,H,hd)
__device__ float g_mlp [ROWS * DFF];             // mlp hidden

// ============================================================================
// Kernel 1: fused latents = sdpa(latents, concat(x,y), concat(x,y), C^-0.5)
// one block per (b, l); 256 threads (8 warps)
// ============================================================================
__global__ void fuse_latents_kernel(const float* __restrict__ x,
                                    const float* __restrict__ y,
                                    const float* __restrict__ lat,
                                    float* __restrict__ fused)
{
    const int b = blockIdx.x / Ll;
    const int l = blockIdx.x % Ll;
    const int tid = threadIdx.x, lane = tid & 31, w = tid >> 5;

    __shared__ float s[NCAT];
    __shared__ float red[64];

    const float* latrow = lat + l * Cc;
    const float scale = 0.03608439182435161f;  // 1/sqrt(768)

    // scores: one n per warp (strided)
    for (int n = w; n < NCAT; n += 8) {
        const float* row = (n < Nn) ? x + (size_t)(b * Nn + n) * Cc
                                    : y + (size_t)(b * Nn + (n - Nn)) * Cc;
        float acc = 0.f;
        for (int c = lane; c < Cc; c += 32) acc += latrow[c] * row[c];
        #pragma unroll
        for (int o = 16; o; o >>= 1) acc += __shfl_xor_sync(0xffffffffu, acc, o);
        if (lane == 0) s[n] = acc * scale;
    }
    __syncthreads();

    // softmax over 392
    float mx = -INFINITY;
    for (int n = tid; n < NCAT; n += 256) mx = fmaxf(mx, s[n]);
    #pragma unroll
    for (int o = 16; o; o >>= 1) mx = fmaxf(mx, __shfl_xor_sync(0xffffffffu, mx, o));
    if (lane == 0) red[w] = mx;
    __syncthreads();
    mx = red[0];
    #pragma unroll
    for (int i = 1; i < 8; i++) mx = fmaxf(mx, red[i]);
    __syncthreads();

    float sum = 0.f;
    for (int n = tid; n < NCAT; n += 256) {
        float e = __expf(s[n] - mx);
        s[n] = e;
        sum += e;
    }
    #pragma unroll
    for (int o = 16; o; o >>= 1) sum += __shfl_xor_sync(0xffffffffu, sum, o);
    if (lane == 0) red[8 + w] = sum;
    __syncthreads();
    sum = 0.f;
    #pragma unroll
    for (int i = 0; i < 8; i++) sum += red[8 + i];
    const float inv = 1.f / sum;
    for (int n = tid; n < NCAT; n += 256) s[n] *= inv;
    __syncthreads();

    // fused[b,l,c] = sum_n w[n] * concat[b,n,c]
    for (int c = tid; c < Cc; c += 256) {
        float acc = 0.f;
        const float* xp = x + (size_t)b * Nn * Cc + c;
        for (int n = 0; n < Nn; n++) acc += s[n] * xp[(size_t)n * Cc];
        const float* yp = y + (size_t)b * Nn * Cc + c;
        for (int n = 0; n < Nn; n++) acc += s[Nn + n] * yp[(size_t)n * Cc];
        fused[(size_t)(b * Ll + l) * Cc + c] = acc;
    }
}

// ============================================================================
// Kernel 2: out = in + scale * sdpa(in, fused, fused, C^-0.5)
// one block per (b*N + n); blockIdx.y selects stream (0 = x, 1 = y)
// ============================================================================
__global__ void cross_attend_kernel(const float* __restrict__ x,
                                    const float* __restrict__ y,
                                    const float* __restrict__ fused,
                                    const float* __restrict__ scale_a,
                                    const float* __restrict__ scale_v,
                                    float* __restrict__ outx,
                                    float* __restrict__ outy)
{
    const int row = blockIdx.x;        // b*N + n
    const int b = row / Nn;
    const int tid = threadIdx.x;

    const float* in;
    float* out;
    float sc;
    if (blockIdx.y == 0) { in = x + (size_t)row * Cc; out = outx + (size_t)row * Cc; sc = *scale_a; }
    else                 { in = y + (size_t)row * Cc; out = outy + (size_t)row * Cc; sc = *scale_v; }

    const float* f = fused + (size_t)b * Ll * Cc;

    __shared__ float red[256];
    __shared__ float w4[Ll];

    float p0 = 0.f, p1 = 0.f, p2 = 0.f, p3 = 0.f;
    for (int c = tid; c < Cc; c += 256) {
        float v = in[c];
        p0 += v * f[c];
        p1 += v * f[Cc + c];
        p2 += v * f[2 * Cc + c];
        p3 += v * f[3 * Cc + c];
    }
    float ps[4] = {p0, p1, p2, p3};
    #pragma unroll
    for (int l = 0; l < Ll; l++) {
        red[tid] = ps[l];
        __syncthreads();
        for (int st = 128; st; st >>= 1) {
            if (tid < st) red[tid] += red[tid + st];
            __syncthreads();
        }
        if (tid == 0) w4[l] = red[0] * 0.03608439182435161f;
        __syncthreads();
    }
    if (tid == 0) {
        float mx = fmaxf(fmaxf(w4[0], w4[1]), fmaxf(w4[2], w4[3]));
        float e0 = __expf(w4[0] - mx), e1 = __expf(w4[1] - mx);
        float e2 = __expf(w4[2] - mx), e3 = __expf(w4[3] - mx);
        float inv = 1.f / (e0 + e1 + e2 + e3);
        w4[0] = e0 * inv; w4[1] = e1 * inv; w4[2] = e2 * inv; w4[3] = e3 * inv;
    }
    __syncthreads();

    const float a0 = w4[0], a1 = w4[1], a2 = w4[2], a3 = w4[3];
    for (int c = tid; c < Cc; c += 256) {
        float r = a0 * f[c] + a1 * f[Cc + c] + a2 * f[2 * Cc + c] + a3 * f[3 * Cc + c];
        out[c] = in[c] + sc * r;
    }
}

// ============================================================================
// LayerNorm: one block per row, 256 threads, C = 768 (3 elems / thread)
// ============================================================================
__global__ void ln_kernel(const float* __restrict__ in,
                          const float* __restrict__ g,
                          const float* __restrict__ bta,
                          float* __restrict__ out)
{
    const int row = blockIdx.x;
    const int tid = threadIdx.x;
    const float* ip = in + (size_t)row * Cc;
    __shared__ float red[256];
    __shared__ float s_mean, s_rstd;

    float v0 = ip[tid], v1 = ip[tid + 256], v2 = ip[tid + 512];
    float sum = v0 + v1 + v2;
    red[tid] = sum;
    __syncthreads();
    for (int st = 128; st; st >>= 1) { if (tid < st) red[tid] += red[tid + st]; __syncthreads(); }
    if (tid == 0) s_mean = red[0] * (1.f / Cc);
    __syncthreads();
    const float mean = s_mean;

    float d0 = v0 - mean, d1 = v1 - mean, d2 = v2 - mean;
    red[tid] = d0 * d0 + d1 * d1 + d2 * d2;
    __syncthreads();
    for (int st = 128; st; st >>= 1) { if (tid < st) red[tid] += red[tid + st]; __syncthreads(); }
    if (tid == 0) s_rstd = rsqrtf(red[0] * (1.f / Cc) + 1e-6f);
    __syncthreads();
    const float rstd = s_rstd;

    float* op = out + (size_t)row * Cc;
    op[tid]       = d0 * rstd * g[tid]       + bta[tid];
    op[tid + 256] = d1 * rstd * g[tid + 256] + bta[tid + 256];
    op[tid + 512] = d2 * rstd * g[tid + 512] + bta[tid + 512];
}

// ============================================================================
// SGEMM: C[M,N] = A[M,K] @ W[K,N] + bias  (+gelu | +residual)
// 128x128 tile, BK=8, 256 threads, 8x8 per thread. M,N mult of 128, K mult of 8.
// EPI: 0 = bias, 1 = bias + exact gelu, 2 = bias + residual
// ============================================================================
template<int EPI>
__global__ __launch_bounds__(256)
void sgemm_kernel(const float* __restrict__ A, const float* __restrict__ W,
                  const float* __restrict__ bias, const float* __restrict__ res,
                  float* __restrict__ C, int M, int N, int K)
{
    __shared__ float As[8][128];
    __shared__ float Bs[8][128];

    const int tid = threadIdx.x;
    const int bm = blockIdx.y * 128;
    const int bn = blockIdx.x * 128;

    const int arow = tid >> 1;            // 0..127
    const int acol = (tid & 1) * 4;       // 0 or 4
    const int brow = tid >> 5;            // 0..7
    const int bcol = (tid & 31) * 4;      // 0..124

    const int ty = tid >> 4;              // 0..15 -> rows ty*8..
    const int tx = tid & 15;              // 0..15 -> cols tx*8..

    float acc[8][8];
    #pragma unroll
    for (int i = 0; i < 8; i++)
        #pragma unroll
        for (int j = 0; j < 8; j++) acc[i][j] = 0.f;

    const float* Aptr = A + (size_t)(bm + arow) * K + acol;
    const float* Bptr = W + (size_t)brow * N + bn + bcol;

    for (int k0 = 0; k0 < K; k0 += 8) {
        float4 av = *(const float4*)Aptr;  Aptr += 8;
        float4 bv = *(const float4*)Bptr;  Bptr += (size_t)8 * N;

        As[acol + 0][arow] = av.x;
        As[acol + 1][arow] = av.y;
        As[acol + 2][arow] = av.z;
        As[acol + 3][arow] = av.w;
        *(float4*)&Bs[brow][bcol] = bv;
        __syncthreads();

        #pragma unroll
        for (int k = 0; k < 8; k++) {
            float ar[8], br[8];
            #pragma unroll
            for (int i = 0; i < 8; i++) ar[i] = As[k][ty * 8 + i];
            #pragma unroll
            for (int j = 0; j < 8; j++) br[j] = Bs[k][tx * 8 + j];
            #pragma unroll
            for (int i = 0; i < 8; i++)
                #pragma unroll
                for (int j = 0; j < 8; j++) acc[i][j] = fmaf(ar[i], br[j], acc[i][j]);
        }
        __syncthreads();
    }

    #pragma unroll
    for (int i = 0; i < 8; i++) {
        const int m = bm + ty * 8 + i;
        #pragma unroll
        for (int j = 0; j < 8; j++) {
            const int n = bn + tx * 8 + j;
            float v = acc[i][j] + bias[n];
            if (EPI == 1) v = v * 0.5f * (1.f + erff(v * 0.70710678118654752f));
            if (EPI == 2) v += res[(size_t)m * N + n];
            C[(size_t)m * N + n] = v;
        }
    }
}

// ============================================================================
// Attention: one block per (b, head); K/V resident in smem (pad stride 65)
// ============================================================================
constexpr int KVSTRIDE = HD + 1;                                    // 65
constexpr int ATTN_SMEM = (2 * Nn * KVSTRIDE + 8 * Nn + 8 * HD) * 4; // 110240 B

__global__ void attn_kernel(const float* __restrict__ qkv, float* __restrict__ o)
{
    extern __shared__ float sm[];
    float* Ks = sm;                          // 196*65
    float* Vs = Ks + Nn * KVSTRIDE;          // 196*65
    float* S  = Vs + Nn * KVSTRIDE;          // 8*196
    float* Qs = S + 8 * Nn;                  // 8*64

    const int bh = blockIdx.x;
    const int b = bh / Hh, hh = bh % Hh;
    const int tid = threadIdx.x, lane = tid & 31, w = tid >> 5;

    const float* qkvb = qkv + (size_t)b * Nn * (3 * Cc);

    for (int idx = tid; idx < Nn * HD; idx += 256) {
        const int n = idx >> 6, d = idx & 63;
        const float* rp = qkvb + (size_t)n * (3 * Cc) + hh * HD + d;
        Ks[n * KVSTRIDE + d] = rp[Cc];        // k at offset 1*C
        Vs[n * KVSTRIDE + d] = rp[2 * Cc];    // v at offset 2*C
    }
    __syncthreads();

    float* Sw = S + w * Nn;
    float* Qw = Qs + w * HD;

    for (int r = w; r < Nn; r += 8) {
        const float* qp = qkvb + (size_t)r * (3 * Cc) + hh * HD;
        Qw[lane] = qp[lane];
        Qw[lane + 32] = qp[lane + 32];
        __syncwarp();

        float mx = -INFINITY;
        for (int k = lane; k < Nn; k += 32) {
            float acc = 0.f;
            #pragma unroll
            for (int d = 0; d < HD; d++) acc = fmaf(Qw[d], Ks[k * KVSTRIDE + d], acc);
            acc *= 0.125f;                    // hd^-0.5
            Sw[k] = acc;
            mx = fmaxf(mx, acc);
        }
        #pragma unroll
        for (int off = 16; off; off >>= 1) mx = fmaxf(mx, __shfl_xor_sync(0xffffffffu, mx, off));

        float sum = 0.f;
        for (int k = lane; k < Nn; k += 32) {
            float e = __expf(Sw[k] - mx);
            Sw[k] = e;
            sum += e;
        }
        #pragma unroll
        for (int off = 16; off; off >>= 1) sum += __shfl_xor_sync(0xffffffffu, sum, off);
        const float inv = 1.f / sum;
        __syncwarp();

        float a0 = 0.f, a1 = 0.f;
        for (int k = 0; k < Nn; k++) {
            const float p = Sw[k];
            a0 = fmaf(p, Vs[k * KVSTRIDE + lane], a0);
            a1 = fmaf(p, Vs[k * KVSTRIDE + lane + 32], a1);
        }
        float* op = o + (size_t)(b * Nn + r) * Cc + hh * HD;
        op[lane] = a0 * inv;
        op[lane + 32] = a1 * inv;
        __syncwarp();
    }
}

// ============================================================================
// host launcher
// ============================================================================
extern "C" void kernel_launch(void* const* d_in, const int* in_sizes, int n_in,
                              void* d_out, int out_size)
{
    const float* x        = (const float*)d_in[0];
    const float* y        = (const float*)d_in[1];
    const float* latents  = (const float*)d_in[2];
    const float* scale_a  = (const float*)d_in[3];
    const float* scale_v  = (const float*)d_in[4];

    // per-stream params: [ln1_g, ln1_b, qkv_w, qkv_b, proj_w, proj_b,
    //                     ln2_g, ln2_b, fc1_w, fc1_b, fc2_w, fc2_b]
    const float* sp[12];
    const float* rp[12];
    for (int i = 0; i < 12; i++) { sp[i] = (const float*)d_in[5 + i]; rp[i] = (const float*)d_in[17 + i]; }

    float* outx = (float*)d_out;
    float* outy = outx + (size_t)ROWS * Cc;

    float *fused, *hbuf, *qkvbuf, *obuf, *mlpbuf;
    cudaGetSymbolAddress((void**)&fused,  g_fused);
    cudaGetSymbolAddress((void**)&hbuf,   g_h);
    cudaGetSymbolAddress((void**)&qkvbuf, g_qkv);
    cudaGetSymbolAddress((void**)&obuf,   g_o);
    cudaGetSymbolAddress((void**)&mlpbuf, g_mlp);

    cudaFuncSetAttribute(attn_kernel, cudaFuncAttributeMaxDynamicSharedMemorySize, ATTN_SMEM);

    // --- latent bottleneck fusion ---
    fuse_latents_kernel<<<Bb * Ll, 256>>>(x, y, latents, fused);
    cross_attend_kernel<<<dim3(ROWS, 2), 256>>>(x, y, fused, scale_a, scale_v, outx, outy);

    // --- ViT block per stream ---
    for (int s = 0; s < 2; s++) {
        const float** P = (s == 0) ? sp : rp;
        float* base = (s == 0) ? outx : outy;

        // LN1 -> qkv
        ln_kernel<<<ROWS, 256>>>(base, P[0], P[1], hbuf);
        sgemm_kernel<0><<<dim3(3 * Cc / 128, ROWS / 128), 256>>>(
            hbuf, P[2], P[3], nullptr, qkvbuf, ROWS, 3 * Cc, Cc);

        // attention
        attn_kernel<<<Bb * Hh, 256, ATTN_SMEM>>>(qkvbuf, obuf);

        // proj + residual (in place on base)
        sgemm_kernel<2><<<dim3(Cc / 128, ROWS / 128), 256>>>(
            obuf, P[4], P[5], base, base, ROWS, Cc, Cc);

        // LN2 -> fc1 (gelu) -> fc2 + residual
        ln_kernel<<<ROWS, 256>>>(base, P[6], P[7], hbuf);
        sgemm_kernel<1><<<dim3(DFF / 128, ROWS / 128), 256>>>(
            hbuf, P[8], P[9], nullptr, mlpbuf, ROWS, DFF, Cc);
        sgemm_kernel<2><<<dim3(Cc / 128, ROWS / 128), 256>>>(
            mlpbuf, P[10], P[11], base, base, ROWS, Cc, DFF);
    }
}

// round 2
// speedup vs baseline: 2.1286x; 2.1286x over previous
#include <cuda_runtime.h>
#include <math.h>
#include <stdint.h>

// ---------------- problem constants ----------------
constexpr int Bb   = 32;
constexpr int Nn   = 196;
constexpr int Cc   = 768;
constexpr int Hh   = 12;
constexpr int Ll   = 4;
constexpr int DFF  = 3072;
constexpr int HD   = Cc / Hh;          // 64
constexpr int ROWS = Bb * Nn;          // 6272
constexpr int NCAT = 2 * Nn;           // 392

// ---------------- scratch (static device memory; no allocation) ----------------
__device__ float g_fused[Bb * Ll * Cc];          // [B,L,C]
__device__ float g_h   [ROWS * Cc];              // LN output
__device__ float g_qkv [ROWS * 3 * Cc];          // qkv projection
__device__ float g_o   [ROWS * Cc];              // attention output (B,N,H,hd)
__device__ float g_mlp [ROWS * DFF];             // mlp hidden

// ============================================================================
// Kernel 1: fused latents = sdpa(latents, concat(x,y), concat(x,y), C^-0.5)
// ============================================================================
__global__ void fuse_latents_kernel(const float* __restrict__ x,
                                    const float* __restrict__ y,
                                    const float* __restrict__ lat,
                                    float* __restrict__ fused)
{
    const int b = blockIdx.x / Ll;
    const int l = blockIdx.x % Ll;
    const int tid = threadIdx.x, lane = tid & 31, w = tid >> 5;

    __shared__ float s[NCAT];
    __shared__ float red[64];

    const float* latrow = lat + l * Cc;
    const float scale = 0.03608439182435161f;  // 1/sqrt(768)

    for (int n = w; n < NCAT; n += 8) {
        const float* row = (n < Nn) ? x + (size_t)(b * Nn + n) * Cc
                                    : y + (size_t)(b * Nn + (n - Nn)) * Cc;
        float acc = 0.f;
        for (int c = lane; c < Cc; c += 32) acc += latrow[c] * row[c];
        #pragma unroll
        for (int o = 16; o; o >>= 1) acc += __shfl_xor_sync(0xffffffffu, acc, o);
        if (lane == 0) s[n] = acc * scale;
    }
    __syncthreads();

    float mx = -INFINITY;
    for (int n = tid; n < NCAT; n += 256) mx = fmaxf(mx, s[n]);
    #pragma unroll
    for (int o = 16; o; o >>= 1) mx = fmaxf(mx, __shfl_xor_sync(0xffffffffu, mx, o));
    if (lane == 0) red[w] = mx;
    __syncthreads();
    mx = red[0];
    #pragma unroll
    for (int i = 1; i < 8; i++) mx = fmaxf(mx, red[i]);
    __syncthreads();

    float sum = 0.f;
    for (int n = tid; n < NCAT; n += 256) {
        float e = __expf(s[n] - mx);
        s[n] = e;
        sum += e;
    }
    #pragma unroll
    for (int o = 16; o; o >>= 1) sum += __shfl_xor_sync(0xffffffffu, sum, o);
    if (lane == 0) red[8 + w] = sum;
    __syncthreads();
    sum = 0.f;
    #pragma unroll
    for (int i = 0; i < 8; i++) sum += red[8 + i];
    const float inv = 1.f / sum;
    for (int n = tid; n < NCAT; n += 256) s[n] *= inv;
    __syncthreads();

    for (int c = tid; c < Cc; c += 256) {
        float acc = 0.f;
        const float* xp = x + (size_t)b * Nn * Cc + c;
        for (int n = 0; n < Nn; n++) acc += s[n] * xp[(size_t)n * Cc];
        const float* yp = y + (size_t)b * Nn * Cc + c;
        for (int n = 0; n < Nn; n++) acc += s[Nn + n] * yp[(size_t)n * Cc];
        fused[(size_t)(b * Ll + l) * Cc + c] = acc;
    }
}

// ============================================================================
// Kernel 2: out = in + scale * sdpa(in, fused, fused, C^-0.5)
// ============================================================================
__global__ void cross_attend_kernel(const float* __restrict__ x,
                                    const float* __restrict__ y,
                                    const float* __restrict__ fused,
                                    const float* __restrict__ scale_a,
                                    const float* __restrict__ scale_v,
                                    float* __restrict__ outx,
                                    float* __restrict__ outy)
{
    const int row = blockIdx.x;
    const int b = row / Nn;
    const int tid = threadIdx.x;

    const float* in;
    float* out;
    float sc;
    if (blockIdx.y == 0) { in = x + (size_t)row * Cc; out = outx + (size_t)row * Cc; sc = *scale_a; }
    else                 { in = y + (size_t)row * Cc; out = outy + (size_t)row * Cc; sc = *scale_v; }

    const float* f = fused + (size_t)b * Ll * Cc;

    __shared__ float red[256];
    __shared__ float w4[Ll];

    float p0 = 0.f, p1 = 0.f, p2 = 0.f, p3 = 0.f;
    for (int c = tid; c < Cc; c += 256) {
        float v = in[c];
        p0 += v * f[c];
        p1 += v * f[Cc + c];
        p2 += v * f[2 * Cc + c];
        p3 += v * f[3 * Cc + c];
    }
    float ps[4] = {p0, p1, p2, p3};
    #pragma unroll
    for (int l = 0; l < Ll; l++) {
        red[tid] = ps[l];
        __syncthreads();
        for (int st = 128; st; st >>= 1) {
            if (tid < st) red[tid] += red[tid + st];
            __syncthreads();
        }
        if (tid == 0) w4[l] = red[0] * 0.03608439182435161f;
        __syncthreads();
    }
    if (tid == 0) {
        float mx = fmaxf(fmaxf(w4[0], w4[1]), fmaxf(w4[2], w4[3]));
        float e0 = __expf(w4[0] - mx), e1 = __expf(w4[1] - mx);
        float e2 = __expf(w4[2] - mx), e3 = __expf(w4[3] - mx);
        float inv = 1.f / (e0 + e1 + e2 + e3);
        w4[0] = e0 * inv; w4[1] = e1 * inv; w4[2] = e2 * inv; w4[3] = e3 * inv;
    }
    __syncthreads();

    const float a0 = w4[0], a1 = w4[1], a2 = w4[2], a3 = w4[3];
    for (int c = tid; c < Cc; c += 256) {
        float r = a0 * f[c] + a1 * f[Cc + c] + a2 * f[2 * Cc + c] + a3 * f[3 * Cc + c];
        out[c] = in[c] + sc * r;
    }
}

// ============================================================================
// LayerNorm
// ============================================================================
__global__ void ln_kernel(const float* __restrict__ in,
                          const float* __restrict__ g,
                          const float* __restrict__ bta,
                          float* __restrict__ out)
{
    const int row = blockIdx.x;
    const int tid = threadIdx.x;
    const float* ip = in + (size_t)row * Cc;
    __shared__ float red[256];
    __shared__ float s_mean, s_rstd;

    float v0 = ip[tid], v1 = ip[tid + 256], v2 = ip[tid + 512];
    float sum = v0 + v1 + v2;
    red[tid] = sum;
    __syncthreads();
    for (int st = 128; st; st >>= 1) { if (tid < st) red[tid] += red[tid + st]; __syncthreads(); }
    if (tid == 0) s_mean = red[0] * (1.f / Cc);
    __syncthreads();
    const float mean = s_mean;

    float d0 = v0 - mean, d1 = v1 - mean, d2 = v2 - mean;
    red[tid] = d0 * d0 + d1 * d1 + d2 * d2;
    __syncthreads();
    for (int st = 128; st; st >>= 1) { if (tid < st) red[tid] += red[tid + st]; __syncthreads(); }
    if (tid == 0) s_rstd = rsqrtf(red[0] * (1.f / Cc) + 1e-6f);
    __syncthreads();
    const float rstd = s_rstd;

    float* op = out + (size_t)row * Cc;
    op[tid]       = d0 * rstd * g[tid]       + bta[tid];
    op[tid + 256] = d1 * rstd * g[tid + 256] + bta[tid + 256];
    op[tid + 512] = d2 * rstd * g[tid + 512] + bta[tid + 512];
}

// ============================================================================
// TF32 tensor-core GEMM: C[M,N] = A[M,K] @ W[K,N] + bias (+gelu | +residual)
// 128x128x16 tile, 256 threads (8 warps = 2x4), warp tile 64x32,
// mma.sync.m16n8k8.tf32, smem double buffer + register prefetch.
// EPI: 0 = bias, 1 = bias + exact gelu, 2 = bias + residual
// ============================================================================
constexpr int GLDA = 136;   // smem stride (floats) for A (k-major: [16][136])
constexpr int GLDB = 136;   // smem stride for B

__device__ __forceinline__ float f2tf32(float x) {
    uint32_t r;
    asm("cvt.rna.tf32.f32 %0, %1;" : "=r"(r) : "f"(x));
    return __uint_as_float(r);
}

// swizzled A smem index: column m XOR'd by 8*((k>>2)&3) -> conflict-free
// on both transposing stores and fragment loads.
__device__ __forceinline__ int a_idx(int k, int m) {
    return k * GLDA + (m ^ (((k >> 2) & 3) << 3));
}

template<int EPI>
__global__ __launch_bounds__(256)
void tf32_gemm_kernel(const float* __restrict__ A, const float* __restrict__ W,
                      const float* __restrict__ bias, const float* __restrict__ res,
                      float* __restrict__ C, int M, int N, int K)
{
    __shared__ float As[2][16 * GLDA];
    __shared__ float Bs[2][16 * GLDB];

    const int tid  = threadIdx.x;
    const int lane = tid & 31;
    const int w    = tid >> 5;
    const int wm   = w >> 2;          // 0..1 -> 64-row slab
    const int wn   = w & 3;           // 0..3 -> 32-col slab
    const int gid  = lane >> 2;       // 0..7
    const int tig  = lane & 3;        // 0..3

    const int bm = blockIdx.y * 128;
    const int bn = blockIdx.x * 128;

    float acc[4][4][4];
    #pragma unroll
    for (int i = 0; i < 4; i++)
        #pragma unroll
        for (int j = 0; j < 4; j++)
            #pragma unroll
            for (int q = 0; q < 4; q++) acc[i][j][q] = 0.f;

    // global-load assignments
    const int am = tid >> 2;            // A row within tile (0..63; +64 second chunk)
    const int ak = (tid & 3) * 4;       // A k offset (0,4,8,12)
    const int brow = tid >> 5;          // B k row (0..7; +8 second chunk)
    const int bcol = (tid & 31) * 4;    // B col (0..124)

    const float* Ap = A + (size_t)(bm + am) * K + ak;
    const float* Bp = W + (size_t)brow * N + bn + bcol;

    const int KT = K / 16;

    // ---- prologue: load tile 0 ----
    float4 pa0 = *(const float4*)(Ap);
    float4 pa1 = *(const float4*)(Ap + (size_t)64 * K);
    float4 pb0 = *(const float4*)(Bp);
    float4 pb1 = *(const float4*)(Bp + (size_t)8 * N);

    int buf = 0;
    {
        float* Ad = As[0];
        Ad[a_idx(ak + 0, am)]      = f2tf32(pa0.x);
        Ad[a_idx(ak + 1, am)]      = f2tf32(pa0.y);
        Ad[a_idx(ak + 2, am)]      = f2tf32(pa0.z);
        Ad[a_idx(ak + 3, am)]      = f2tf32(pa0.w);
        Ad[a_idx(ak + 0, am + 64)] = f2tf32(pa1.x);
        Ad[a_idx(ak + 1, am + 64)] = f2tf32(pa1.y);
        Ad[a_idx(ak + 2, am + 64)] = f2tf32(pa1.z);
        Ad[a_idx(ak + 3, am + 64)] = f2tf32(pa1.w);
        *(float4*)&Bs[0][brow * GLDB + bcol] =
            make_float4(f2tf32(pb0.x), f2tf32(pb0.y), f2tf32(pb0.z), f2tf32(pb0.w));
        *(float4*)&Bs[0][(brow + 8) * GLDB + bcol] =
            make_float4(f2tf32(pb1.x), f2tf32(pb1.y), f2tf32(pb1.z), f2tf32(pb1.w));
    }
    __syncthreads();

    for (int kt = 0; kt < KT; kt++) {
        // prefetch next tile into registers
        if (kt + 1 < KT) {
            const float* Ap2 = Ap + (kt + 1) * 16;
            const float* Bp2 = Bp + (size_t)(kt + 1) * 16 * N;
            pa0 = *(const float4*)(Ap2);
            pa1 = *(const float4*)(Ap2 + (size_t)64 * K);
            pb0 = *(const float4*)(Bp2);
            pb1 = *(const float4*)(Bp2 + (size_t)8 * N);
        }

        // compute on current buffer
        const float* Ab = As[buf];
        const float* Bb = Bs[buf];
        #pragma unroll
        for (int ks = 0; ks < 2; ks++) {
            const int k0 = ks * 8 + tig;          // k rows tig / tig+4 within half
            const int sw0 = (ks ? 16 : 0);        // swizzle const for k0 (k>>2 even)
            const int sw1 = sw0 ^ 8;              // swizzle const for k0+4

            uint32_t af[4][4];
            #pragma unroll
            for (int i = 0; i < 4; i++) {
                const int mrow = wm * 64 + i * 16 + gid;
                af[i][0] = __float_as_uint(Ab[k0 * GLDA       + (mrow ^ sw0)]);
                af[i][1] = __float_as_uint(Ab[k0 * GLDA       + ((mrow + 8) ^ sw0)]);
                af[i][2] = __float_as_uint(Ab[(k0 + 4) * GLDA + (mrow ^ sw1)]);
                af[i][3] = __float_as_uint(Ab[(k0 + 4) * GLDA + ((mrow + 8) ^ sw1)]);
            }
            uint32_t bf[4][2];
            #pragma unroll
            for (int j = 0; j < 4; j++) {
                const int ncol = wn * 32 + j * 8 + gid;
                bf[j][0] = __float_as_uint(Bb[k0 * GLDB + ncol]);
                bf[j][1] = __float_as_uint(Bb[(k0 + 4) * GLDB + ncol]);
            }
            #pragma unroll
            for (int i = 0; i < 4; i++)
                #pragma unroll
                for (int j = 0; j < 4; j++) {
                    asm volatile(
                        "mma.sync.aligned.m16n8k8.row.col.f32.tf32.tf32.f32 "
                        "{%0,%1,%2,%3}, {%4,%5,%6,%7}, {%8,%9}, {%0,%1,%2,%3};"
                        : "+f"(acc[i][j][0]), "+f"(acc[i][j][1]),
                          "+f"(acc[i][j][2]), "+f"(acc[i][j][3])
                        : "r"(af[i][0]), "r"(af[i][1]), "r"(af[i][2]), "r"(af[i][3]),
                          "r"(bf[j][0]), "r"(bf[j][1]));
                }
        }

        // store prefetched tile into other buffer
        if (kt + 1 < KT) {
            const int nb = buf ^ 1;
            float* Ad = As[nb];
            Ad[a_idx(ak + 0, am)]      = f2tf32(pa0.x);
            Ad[a_idx(ak + 1, am)]      = f2tf32(pa0.y);
            Ad[a_idx(ak + 2, am)]      = f2tf32(pa0.z);
            Ad[a_idx(ak + 3, am)]      = f2tf32(pa0.w);
            Ad[a_idx(ak + 0, am + 64)] = f2tf32(pa1.x);
            Ad[a_idx(ak + 1, am + 64)] = f2tf32(pa1.y);
            Ad[a_idx(ak + 2, am + 64)] = f2tf32(pa1.z);
            Ad[a_idx(ak + 3, am + 64)] = f2tf32(pa1.w);
            *(float4*)&Bs[nb][brow * GLDB + bcol] =
                make_float4(f2tf32(pb0.x), f2tf32(pb0.y), f2tf32(pb0.z), f2tf32(pb0.w));
            *(float4*)&Bs[nb][(brow + 8) * GLDB + bcol] =
                make_float4(f2tf32(pb1.x), f2tf32(pb1.y), f2tf32(pb1.z), f2tf32(pb1.w));
            __syncthreads();
            buf = nb;
        }
    }

    // ---- epilogue ----
    #pragma unroll
    for (int i = 0; i < 4; i++) {
        const int r0 = bm + wm * 64 + i * 16 + gid;
        #pragma unroll
        for (int j = 0; j < 4; j++) {
            const int c = bn + wn * 32 + j * 8 + tig * 2;
            const float b0 = bias[c], b1 = bias[c + 1];

            float v0 = acc[i][j][0] + b0;
            float v1 = acc[i][j][1] + b1;
            float v2 = acc[i][j][2] + b0;
            float v3 = acc[i][j][3] + b1;
            if (EPI == 1) {
                v0 = v0 * 0.5f * (1.f + erff(v0 * 0.70710678118654752f));
                v1 = v1 * 0.5f * (1.f + erff(v1 * 0.70710678118654752f));
                v2 = v2 * 0.5f * (1.f + erff(v2 * 0.70710678118654752f));
                v3 = v3 * 0.5f * (1.f + erff(v3 * 0.70710678118654752f));
            }
            if (EPI == 2) {
                const float* r = res + (size_t)r0 * N + c;
                v0 += r[0]; v1 += r[1];
                const float* r2 = res + (size_t)(r0 + 8) * N + c;
                v2 += r2[0]; v3 += r2[1];
            }
            *(float2*)&C[(size_t)r0 * N + c]       = make_float2(v0, v1);
            *(float2*)&C[(size_t)(r0 + 8) * N + c] = make_float2(v2, v3);
        }
    }
}

// ============================================================================
// Attention: one block per (b, head); K/V resident in smem (pad stride 65)
// ============================================================================
constexpr int KVSTRIDE = HD + 1;                                    // 65
constexpr int ATTN_SMEM = (2 * Nn * KVSTRIDE + 8 * Nn + 8 * HD) * 4; // 110240 B

__global__ void attn_kernel(const float* __restrict__ qkv, float* __restrict__ o)
{
    extern __shared__ float sm[];
    float* Ks = sm;
    float* Vs = Ks + Nn * KVSTRIDE;
    float* S  = Vs + Nn * KVSTRIDE;
    float* Qs = S + 8 * Nn;

    const int bh = blockIdx.x;
    const int b = bh / Hh, hh = bh % Hh;
    const int tid = threadIdx.x, lane = tid & 31, w = tid >> 5;

    const float* qkvb = qkv + (size_t)b * Nn * (3 * Cc);

    for (int idx = tid; idx < Nn * HD; idx += 256) {
        const int n = idx >> 6, d = idx & 63;
        const float* rp = qkvb + (size_t)n * (3 * Cc) + hh * HD + d;
        Ks[n * KVSTRIDE + d] = rp[Cc];
        Vs[n * KVSTRIDE + d] = rp[2 * Cc];
    }
    __syncthreads();

    float* Sw = S + w * Nn;
    float* Qw = Qs + w * HD;

    for (int r = w; r < Nn; r += 8) {
        const float* qp = qkvb + (size_t)r * (3 * Cc) + hh * HD;
        Qw[lane] = qp[lane];
        Qw[lane + 32] = qp[lane + 32];
        __syncwarp();

        float mx = -INFINITY;
        for (int k = lane; k < Nn; k += 32) {
            float acc = 0.f;
            #pragma unroll
            for (int d = 0; d < HD; d++) acc = fmaf(Qw[d], Ks[k * KVSTRIDE + d], acc);
            acc *= 0.125f;
            Sw[k] = acc;
            mx = fmaxf(mx, acc);
        }
        #pragma unroll
        for (int off = 16; off; off >>= 1) mx = fmaxf(mx, __shfl_xor_sync(0xffffffffu, mx, off));

        float sum = 0.f;
        for (int k = lane; k < Nn; k += 32) {
            float e = __expf(Sw[k] - mx);
            Sw[k] = e;
            sum += e;
        }
        #pragma unroll
        for (int off = 16; off; off >>= 1) sum += __shfl_xor_sync(0xffffffffu, sum, off);
        const float inv = 1.f / sum;
        __syncwarp();

        float a0 = 0.f, a1 = 0.f;
        for (int k = 0; k < Nn; k++) {
            const float p = Sw[k];
            a0 = fmaf(p, Vs[k * KVSTRIDE + lane], a0);
            a1 = fmaf(p, Vs[k * KVSTRIDE + lane + 32], a1);
        }
        float* op = o + (size_t)(b * Nn + r) * Cc + hh * HD;
        op[lane] = a0 * inv;
        op[lane + 32] = a1 * inv;
        __syncwarp();
    }
}

// ============================================================================
// host launcher
// ============================================================================
extern "C" void kernel_launch(void* const* d_in, const int* in_sizes, int n_in,
                              void* d_out, int out_size)
{
    const float* x        = (const float*)d_in[0];
    const float* y        = (const float*)d_in[1];
    const float* latents  = (const float*)d_in[2];
    const float* scale_a  = (const float*)d_in[3];
    const float* scale_v  = (const float*)d_in[4];

    const float* sp[12];
    const float* rp[12];
    for (int i = 0; i < 12; i++) { sp[i] = (const float*)d_in[5 + i]; rp[i] = (const float*)d_in[17 + i]; }

    float* outx = (float*)d_out;
    float* outy = outx + (size_t)ROWS * Cc;

    float *fused, *hbuf, *qkvbuf, *obuf, *mlpbuf;
    cudaGetSymbolAddress((void**)&fused,  g_fused);
    cudaGetSymbolAddress((void**)&hbuf,   g_h);
    cudaGetSymbolAddress((void**)&qkvbuf, g_qkv);
    cudaGetSymbolAddress((void**)&obuf,   g_o);
    cudaGetSymbolAddress((void**)&mlpbuf, g_mlp);

    cudaFuncSetAttribute(attn_kernel, cudaFuncAttributeMaxDynamicSharedMemorySize, ATTN_SMEM);

    // --- latent bottleneck fusion ---
    fuse_latents_kernel<<<Bb * Ll, 256>>>(x, y, latents, fused);
    cross_attend_kernel<<<dim3(ROWS, 2), 256>>>(x, y, fused, scale_a, scale_v, outx, outy);

    // --- ViT block per stream ---
    for (int s = 0; s < 2; s++) {
        const float** P = (s == 0) ? sp : rp;
        float* base = (s == 0) ? outx : outy;

        ln_kernel<<<ROWS, 256>>>(base, P[0], P[1], hbuf);
        tf32_gemm_kernel<0><<<dim3(3 * Cc / 128, ROWS / 128), 256>>>(
            hbuf, P[2], P[3], nullptr, qkvbuf, ROWS, 3 * Cc, Cc);

        attn_kernel<<<Bb * Hh, 256, ATTN_SMEM>>>(qkvbuf, obuf);

        tf32_gemm_kernel<2><<<dim3(Cc / 128, ROWS / 128), 256>>>(
            obuf, P[4], P[5], base, base, ROWS, Cc, Cc);

        ln_kernel<<<ROWS, 256>>>(base, P[6], P[7], hbuf);
        tf32_gemm_kernel<1><<<dim3(DFF / 128, ROWS / 128), 256>>>(
            hbuf, P[8], P[9], nullptr, mlpbuf, ROWS, DFF, Cc);
        tf32_gemm_kernel<2><<<dim3(Cc / 128, ROWS / 128), 256>>>(
            mlpbuf, P[10], P[11], base, base, ROWS, Cc, DFF);
    }
}

// round 3
// speedup vs baseline: 2.3112x; 1.0858x over previous
#include <cuda_runtime.h>
#include <math.h>
#include <stdint.h>

// ---------------- problem constants ----------------
constexpr int Bb   = 32;
constexpr int Nn   = 196;
constexpr int Cc   = 768;
constexpr int Hh   = 12;
constexpr int Ll   = 4;
constexpr int DFF  = 3072;
constexpr int HD   = Cc / Hh;          // 64
constexpr int ROWS = Bb * Nn;          // 6272
constexpr int NCAT = 2 * Nn;           // 392

// ---------------- scratch (static device memory; no allocation) ----------------
__device__ float g_fused[Bb * Ll * Cc];
__device__ float g_h   [2 * ROWS * Cc];
__device__ float g_qkv [2 * ROWS * 3 * Cc];
__device__ float g_o   [2 * ROWS * Cc];
__device__ float g_mlp [2 * ROWS * DFF];

// ============================================================================
// Kernel 1: fused latents = sdpa(latents, concat(x,y), concat(x,y), C^-0.5)
// ============================================================================
__global__ void fuse_latents_kernel(const float* __restrict__ x,
                                    const float* __restrict__ y,
                                    const float* __restrict__ lat,
                                    float* __restrict__ fused)
{
    const int b = blockIdx.x / Ll;
    const int l = blockIdx.x % Ll;
    const int tid = threadIdx.x, lane = tid & 31, w = tid >> 5;

    __shared__ float s[NCAT];
    __shared__ float red[64];

    const float* latrow = lat + l * Cc;
    const float scale = 0.03608439182435161f;  // 1/sqrt(768)

    for (int n = w; n < NCAT; n += 8) {
        const float* row = (n < Nn) ? x + (size_t)(b * Nn + n) * Cc
                                    : y + (size_t)(b * Nn + (n - Nn)) * Cc;
        float acc = 0.f;
        for (int c = lane; c < Cc; c += 32) acc += latrow[c] * row[c];
        #pragma unroll
        for (int o = 16; o; o >>= 1) acc += __shfl_xor_sync(0xffffffffu, acc, o);
        if (lane == 0) s[n] = acc * scale;
    }
    __syncthreads();

    float mx = -INFINITY;
    for (int n = tid; n < NCAT; n += 256) mx = fmaxf(mx, s[n]);
    #pragma unroll
    for (int o = 16; o; o >>= 1) mx = fmaxf(mx, __shfl_xor_sync(0xffffffffu, mx, o));
    if (lane == 0) red[w] = mx;
    __syncthreads();
    mx = red[0];
    #pragma unroll
    for (int i = 1; i < 8; i++) mx = fmaxf(mx, red[i]);
    __syncthreads();

    float sum = 0.f;
    for (int n = tid; n < NCAT; n += 256) {
        float e = __expf(s[n] - mx);
        s[n] = e;
        sum += e;
    }
    #pragma unroll
    for (int o = 16; o; o >>= 1) sum += __shfl_xor_sync(0xffffffffu, sum, o);
    if (lane == 0) red[8 + w] = sum;
    __syncthreads();
    sum = 0.f;
    #pragma unroll
    for (int i = 0; i < 8; i++) sum += red[8 + i];
    const float inv = 1.f / sum;
    for (int n = tid; n < NCAT; n += 256) s[n] *= inv;
    __syncthreads();

    for (int c = tid; c < Cc; c += 256) {
        float acc = 0.f;
        const float* xp = x + (size_t)b * Nn * Cc + c;
        for (int n = 0; n < Nn; n++) acc += s[n] * xp[(size_t)n * Cc];
        const float* yp = y + (size_t)b * Nn * Cc + c;
        for (int n = 0; n < Nn; n++) acc += s[Nn + n] * yp[(size_t)n * Cc];
        fused[(size_t)(b * Ll + l) * Cc + c] = acc;
    }
}

// ============================================================================
// Kernel 2: out = in + scale * sdpa(in, fused, fused, C^-0.5)
// ============================================================================
__global__ void cross_attend_kernel(const float* __restrict__ x,
                                    const float* __restrict__ y,
                                    const float* __restrict__ fused,
                                    const float* __restrict__ scale_a,
                                    const float* __restrict__ scale_v,
                                    float* __restrict__ outx,
                                    float* __restrict__ outy)
{
    const int row = blockIdx.x;
    const int b = row / Nn;
    const int tid = threadIdx.x;

    const float* in;
    float* out;
    float sc;
    if (blockIdx.y == 0) { in = x + (size_t)row * Cc; out = outx + (size_t)row * Cc; sc = *scale_a; }
    else                 { in = y + (size_t)row * Cc; out = outy + (size_t)row * Cc; sc = *scale_v; }

    const float* f = fused + (size_t)b * Ll * Cc;

    __shared__ float red[256];
    __shared__ float w4[Ll];

    float p0 = 0.f, p1 = 0.f, p2 = 0.f, p3 = 0.f;
    for (int c = tid; c < Cc; c += 256) {
        float v = in[c];
        p0 += v * f[c];
        p1 += v * f[Cc + c];
        p2 += v * f[2 * Cc + c];
        p3 += v * f[3 * Cc + c];
    }
    float ps[4] = {p0, p1, p2, p3};
    #pragma unroll
    for (int l = 0; l < Ll; l++) {
        red[tid] = ps[l];
        __syncthreads();
        for (int st = 128; st; st >>= 1) {
            if (tid < st) red[tid] += red[tid + st];
            __syncthreads();
        }
        if (tid == 0) w4[l] = red[0] * 0.03608439182435161f;
        __syncthreads();
    }
    if (tid == 0) {
        float mx = fmaxf(fmaxf(w4[0], w4[1]), fmaxf(w4[2], w4[3]));
        float e0 = __expf(w4[0] - mx), e1 = __expf(w4[1] - mx);
        float e2 = __expf(w4[2] - mx), e3 = __expf(w4[3] - mx);
        float inv = 1.f / (e0 + e1 + e2 + e3);
        w4[0] = e0 * inv; w4[1] = e1 * inv; w4[2] = e2 * inv; w4[3] = e3 * inv;
    }
    __syncthreads();

    const float a0 = w4[0], a1 = w4[1], a2 = w4[2], a3 = w4[3];
    for (int c = tid; c < Cc; c += 256) {
        float r = a0 * f[c] + a1 * f[Cc + c] + a2 * f[2 * Cc + c] + a3 * f[3 * Cc + c];
        out[c] = in[c] + sc * r;
    }
}

// ============================================================================
// LayerNorm (batched over 2 streams via blockIdx.y)
// ============================================================================
__global__ void ln_kernel(const float* __restrict__ inb,
                          const float* __restrict__ g0, const float* __restrict__ b0,
                          const float* __restrict__ g1, const float* __restrict__ b1,
                          float* __restrict__ outb)
{
    const int z = blockIdx.y;
    const int row = blockIdx.x;
    const int tid = threadIdx.x;
    const float* g   = z ? g1 : g0;
    const float* bta = z ? b1 : b0;
    const float* ip = inb  + ((size_t)z * ROWS + row) * Cc;
    float*       op = outb + ((size_t)z * ROWS + row) * Cc;

    __shared__ float red[256];
    __shared__ float s_mean, s_rstd;

    float v0 = ip[tid], v1 = ip[tid + 256], v2 = ip[tid + 512];
    float sum = v0 + v1 + v2;
    red[tid] = sum;
    __syncthreads();
    for (int st = 128; st; st >>= 1) { if (tid < st) red[tid] += red[tid + st]; __syncthreads(); }
    if (tid == 0) s_mean = red[0] * (1.f / Cc);
    __syncthreads();
    const float mean = s_mean;

    float d0 = v0 - mean, d1 = v1 - mean, d2 = v2 - mean;
    red[tid] = d0 * d0 + d1 * d1 + d2 * d2;
    __syncthreads();
    for (int st = 128; st; st >>= 1) { if (tid < st) red[tid] += red[tid + st]; __syncthreads(); }
    if (tid == 0) s_rstd = rsqrtf(red[0] * (1.f / Cc) + 1e-6f);
    __syncthreads();
    const float rstd = s_rstd;

    op[tid]       = d0 * rstd * g[tid]       + bta[tid];
    op[tid + 256] = d1 * rstd * g[tid + 256] + bta[tid + 256];
    op[tid + 512] = d2 * rstd * g[tid + 512] + bta[tid + 512];
}

// ============================================================================
// TF32 tensor-core GEMM, cp.async pipelined, batched over 2 streams (blockIdx.z)
// C_z[M,N] = A_z[M,K] @ W_z[K,N] + bias_z (+gelu | +residual_z)
// 128x128x16 tile, 256 threads (8 warps 2x4), warp tile 64x32, m16n8k8.tf32.
// A smem m-major [128][20] (20%32 -> conflict-free frag loads); B k-major [16][136].
// fp32 fed raw to mma (RZ truncation to tf32) -- no cvt in the hot loop.
// ============================================================================
constexpr int LDA = 20;
constexpr int LDB = 136;

__device__ __forceinline__ void cp_async16(uint32_t s, const void* g) {
    asm volatile("cp.async.ca.shared.global [%0], [%1], 16;" :: "r"(s), "l"(g));
}
__device__ __forceinline__ void cp_commit() {
    asm volatile("cp.async.commit_group;");
}
__device__ __forceinline__ void cp_wait0() {
    asm volatile("cp.async.wait_group 0;");
}

template<int EPI>
__global__ __launch_bounds__(256)
void tf32_gemm_kernel(const float* __restrict__ Abase, size_t strideA,
                      const float* __restrict__ W0, const float* __restrict__ W1,
                      const float* __restrict__ bias0, const float* __restrict__ bias1,
                      const float* __restrict__ resbase,
                      float* __restrict__ Cbase, size_t strideC,
                      int M, int N, int K)
{
    __shared__ float As[2][128 * LDA];
    __shared__ float Bs[2][16 * LDB];

    const int z = blockIdx.z;
    const float* A    = Abase + (size_t)z * strideA;
    const float* W    = z ? W1 : W0;
    const float* bias = z ? bias1 : bias0;
    const float* res  = (EPI == 2) ? resbase + (size_t)z * strideC : nullptr;
    float*       C    = Cbase + (size_t)z * strideC;

    const int tid  = threadIdx.x;
    const int lane = tid & 31;
    const int w    = tid >> 5;
    const int wm   = w >> 2;
    const int wn   = w & 3;
    const int gid  = lane >> 2;
    const int tig  = lane & 3;

    const int bm = blockIdx.y * 128;
    const int bn = blockIdx.x * 128;

    float acc[4][4][4];
    #pragma unroll
    for (int i = 0; i < 4; i++)
        #pragma unroll
        for (int j = 0; j < 4; j++)
            #pragma unroll
            for (int q = 0; q < 4; q++) acc[i][j][q] = 0.f;

    // global-load assignments
    const int ar = tid >> 2;            // 0..63 (A row; second chunk +64)
    const int ac = (tid & 3) * 4;       // k offset within 16
    const int bkr = tid >> 5;           // 0..7  (B k row; second chunk +8)
    const int bc = (tid & 31) * 4;      // B col

    const float* Ap = A + (size_t)(bm + ar) * K + ac;
    const float* Bp = W + (size_t)bkr * N + bn + bc;

    uint32_t sA0 = (uint32_t)__cvta_generic_to_shared(&As[0][ar * LDA + ac]);
    uint32_t sA1 = (uint32_t)__cvta_generic_to_shared(&As[1][ar * LDA + ac]);
    uint32_t sB0 = (uint32_t)__cvta_generic_to_shared(&Bs[0][bkr * LDB + bc]);
    uint32_t sB1 = (uint32_t)__cvta_generic_to_shared(&Bs[1][bkr * LDB + bc]);

    const int KT = K / 16;

    auto load_tile = [&](int kt, int b) {
        const float* a = Ap + kt * 16;
        const float* bsrc = Bp + (size_t)kt * 16 * N;
        uint32_t sa = b ? sA1 : sA0;
        uint32_t sb = b ? sB1 : sB0;
        cp_async16(sa, a);
        cp_async16(sa + 64 * LDA * 4, a + (size_t)64 * K);
        cp_async16(sb, bsrc);
        cp_async16(sb + 8 * LDB * 4, bsrc + (size_t)8 * N);
        cp_commit();
    };

    load_tile(0, 0);
    cp_wait0();
    __syncthreads();

    const int abase = (wm * 64 + gid) * LDA + tig;
    const int bbase = tig * LDB + wn * 32 + gid;

    int buf = 0;
    for (int kt = 0; kt < KT; kt++) {
        if (kt + 1 < KT) load_tile(kt + 1, buf ^ 1);

        const float* Ab = As[buf];
        const float* Bb = Bs[buf];
        #pragma unroll
        for (int ks = 0; ks < 2; ks++) {
            uint32_t af[4][4];
            #pragma unroll
            for (int i = 0; i < 4; i++) {
                const int a0 = abase + i * 16 * LDA + ks * 8;
                af[i][0] = __float_as_uint(Ab[a0]);
                af[i][1] = __float_as_uint(Ab[a0 + 8 * LDA]);
                af[i][2] = __float_as_uint(Ab[a0 + 4]);
                af[i][3] = __float_as_uint(Ab[a0 + 8 * LDA + 4]);
            }
            uint32_t bf[4][2];
            #pragma unroll
            for (int j = 0; j < 4; j++) {
                const int b0 = bbase + ks * 8 * LDB + j * 8;
                bf[j][0] = __float_as_uint(Bb[b0]);
                bf[j][1] = __float_as_uint(Bb[b0 + 4 * LDB]);
            }
            #pragma unroll
            for (int i = 0; i < 4; i++)
                #pragma unroll
                for (int j = 0; j < 4; j++) {
                    asm volatile(
                        "mma.sync.aligned.m16n8k8.row.col.f32.tf32.tf32.f32 "
                        "{%0,%1,%2,%3}, {%4,%5,%6,%7}, {%8,%9}, {%0,%1,%2,%3};"
                        : "+f"(acc[i][j][0]), "+f"(acc[i][j][1]),
                          "+f"(acc[i][j][2]), "+f"(acc[i][j][3])
                        : "r"(af[i][0]), "r"(af[i][1]), "r"(af[i][2]), "r"(af[i][3]),
                          "r"(bf[j][0]), "r"(bf[j][1]));
                }
        }

        if (kt + 1 < KT) {
            cp_wait0();
            __syncthreads();
            buf ^= 1;
        }
    }

    // ---- epilogue ----
    #pragma unroll
    for (int i = 0; i < 4; i++) {
        const int r0 = bm + wm * 64 + i * 16 + gid;
        #pragma unroll
        for (int j = 0; j < 4; j++) {
            const int c = bn + wn * 32 + j * 8 + tig * 2;
            const float b0 = bias[c], b1 = bias[c + 1];

            float v0 = acc[i][j][0] + b0;
            float v1 = acc[i][j][1] + b1;
            float v2 = acc[i][j][2] + b0;
            float v3 = acc[i][j][3] + b1;
            if (EPI == 1) {
                v0 = v0 * 0.5f * (1.f + erff(v0 * 0.70710678118654752f));
                v1 = v1 * 0.5f * (1.f + erff(v1 * 0.70710678118654752f));
                v2 = v2 * 0.5f * (1.f + erff(v2 * 0.70710678118654752f));
                v3 = v3 * 0.5f * (1.f + erff(v3 * 0.70710678118654752f));
            }
            if (EPI == 2) {
                const float* r = res + (size_t)r0 * N + c;
                v0 += r[0]; v1 += r[1];
                const float* r2 = res + (size_t)(r0 + 8) * N + c;
                v2 += r2[0]; v3 += r2[1];
            }
            *(float2*)&C[(size_t)r0 * N + c]       = make_float2(v0, v1);
            *(float2*)&C[(size_t)(r0 + 8) * N + c] = make_float2(v2, v3);
        }
    }
}

// ============================================================================
// Attention: one block per (b, head); batched over streams via blockIdx.y
// ============================================================================
constexpr int KVSTRIDE = HD + 1;                                    // 65
constexpr int ATTN_SMEM = (2 * Nn * KVSTRIDE + 8 * Nn + 8 * HD) * 4; // 110240 B

__global__ void attn_kernel(const float* __restrict__ qkvb_, float* __restrict__ ob_)
{
    extern __shared__ float sm[];
    float* Ks = sm;
    float* Vs = Ks + Nn * KVSTRIDE;
    float* S  = Vs + Nn * KVSTRIDE;
    float* Qs = S + 8 * Nn;

    const int z = blockIdx.y;
    const int bh = blockIdx.x;
    const int b = bh / Hh, hh = bh % Hh;
    const int tid = threadIdx.x, lane = tid & 31, w = tid >> 5;

    const float* qkvb = qkvb_ + (size_t)z * ROWS * 3 * Cc + (size_t)b * Nn * (3 * Cc);
    float* o = ob_ + (size_t)z * ROWS * Cc;

    for (int idx = tid; idx < Nn * HD; idx += 256) {
        const int n = idx >> 6, d = idx & 63;
        const float* rp = qkvb + (size_t)n * (3 * Cc) + hh * HD + d;
        Ks[n * KVSTRIDE + d] = rp[Cc];
        Vs[n * KVSTRIDE + d] = rp[2 * Cc];
    }
    __syncthreads();

    float* Sw = S + w * Nn;
    float* Qw = Qs + w * HD;

    for (int r = w; r < Nn; r += 8) {
        const float* qp = qkvb + (size_t)r * (3 * Cc) + hh * HD;
        Qw[lane] = qp[lane];
        Qw[lane + 32] = qp[lane + 32];
        __syncwarp();

        float mx = -INFINITY;
        for (int k = lane; k < Nn; k += 32) {
            float acc = 0.f;
            #pragma unroll
            for (int d = 0; d < HD; d++) acc = fmaf(Qw[d], Ks[k * KVSTRIDE + d], acc);
            acc *= 0.125f;
            Sw[k] = acc;
            mx = fmaxf(mx, acc);
        }
        #pragma unroll
        for (int off = 16; off; off >>= 1) mx = fmaxf(mx, __shfl_xor_sync(0xffffffffu, mx, off));

        float sum = 0.f;
        for (int k = lane; k < Nn; k += 32) {
            float e = __expf(Sw[k] - mx);
            Sw[k] = e;
            sum += e;
        }
        #pragma unroll
        for (int off = 16; off; off >>= 1) sum += __shfl_xor_sync(0xffffffffu, sum, off);
        const float inv = 1.f / sum;
        __syncwarp();

        float a0 = 0.f, a1 = 0.f;
        for (int k = 0; k < Nn; k++) {
            const float p = Sw[k];
            a0 = fmaf(p, Vs[k * KVSTRIDE + lane], a0);
            a1 = fmaf(p, Vs[k * KVSTRIDE + lane + 32], a1);
        }
        float* op = o + (size_t)(b * Nn + r) * Cc + hh * HD;
        op[lane] = a0 * inv;
        op[lane + 32] = a1 * inv;
        __syncwarp();
    }
}

// ============================================================================
// host launcher
// ============================================================================
extern "C" void kernel_launch(void* const* d_in, const int* in_sizes, int n_in,
                              void* d_out, int out_size)
{
    const float* x        = (const float*)d_in[0];
    const float* y        = (const float*)d_in[1];
    const float* latents  = (const float*)d_in[2];
    const float* scale_a  = (const float*)d_in[3];
    const float* scale_v  = (const float*)d_in[4];

    const float* sp[12];
    const float* rp[12];
    for (int i = 0; i < 12; i++) { sp[i] = (const float*)d_in[5 + i]; rp[i] = (const float*)d_in[17 + i]; }

    float* outx = (float*)d_out;                       // stream 0 output
    // stream 1 output = outx + ROWS*Cc (contiguous)

    float *fused, *hbuf, *qkvbuf, *obuf, *mlpbuf;
    cudaGetSymbolAddress((void**)&fused,  g_fused);
    cudaGetSymbolAddress((void**)&hbuf,   g_h);
    cudaGetSymbolAddress((void**)&qkvbuf, g_qkv);
    cudaGetSymbolAddress((void**)&obuf,   g_o);
    cudaGetSymbolAddress((void**)&mlpbuf, g_mlp);

    cudaFuncSetAttribute(attn_kernel, cudaFuncAttributeMaxDynamicSharedMemorySize, ATTN_SMEM);

    const size_t sC   = (size_t)ROWS * Cc;
    const size_t sQKV = (size_t)ROWS * 3 * Cc;
    const size_t sMLP = (size_t)ROWS * DFF;

    // --- latent bottleneck fusion ---
    fuse_latents_kernel<<<Bb * Ll, 256>>>(x, y, latents, fused);
    cross_attend_kernel<<<dim3(ROWS, 2), 256>>>(x, y, fused, scale_a, scale_v,
                                                outx, outx + sC);

    // --- ViT blocks, both streams batched over blockIdx.z ---
    // LN1 -> qkv
    ln_kernel<<<dim3(ROWS, 2), 256>>>(outx, sp[0], sp[1], rp[0], rp[1], hbuf);
    tf32_gemm_kernel<0><<<dim3(3 * Cc / 128, ROWS / 128, 2), 256>>>(
        hbuf, sC, sp[2], rp[2], sp[3], rp[3], nullptr, qkvbuf, sQKV,
        ROWS, 3 * Cc, Cc);

    // attention
    attn_kernel<<<dim3(Bb * Hh, 2), 256, ATTN_SMEM>>>(qkvbuf, obuf);

    // proj + residual (in place on out)
    tf32_gemm_kernel<2><<<dim3(Cc / 128, ROWS / 128, 2), 256>>>(
        obuf, sC, sp[4], rp[4], sp[5], rp[5], outx, outx, sC,
        ROWS, Cc, Cc);

    // LN2 -> fc1 (gelu) -> fc2 + residual
    ln_kernel<<<dim3(ROWS, 2), 256>>>(outx, sp[6], sp[7], rp[6], rp[7], hbuf);
    tf32_gemm_kernel<1><<<dim3(DFF / 128, ROWS / 128, 2), 256>>>(
        hbuf, sC, sp[8], rp[8], sp[9], rp[9], nullptr, mlpbuf, sMLP,
        ROWS, DFF, Cc);
    tf32_gemm_kernel<2><<<dim3(Cc / 128, ROWS / 128, 2), 256>>>(
        mlpbuf, sMLP, sp[10], rp[10], sp[11], rp[11], outx, outx, sC,
        ROWS, Cc, DFF);
}